// round 5
// baseline (speedup 1.0000x reference)
#include <cuda_runtime.h>
#include <cuda_fp16.h>
#include <math.h>

#define TPB   512
#define HALF_T 256              // producers = threads [256,512), consumers = [0,256)
#define CNT   8192              // points per group
#define SPG   8192              // pairs per group
#define BUF_H2 (3 * CNT)        // half2 slots per buffer (12 B/point) = 96 KB
#define SMEM_BYTES (2 * BUF_H2 * 4)  // 192 KB double buffer

__device__ double g_acc = 0.0;
__device__ unsigned int g_count = 0;

// Stage one group: interleaved layout per point p:
//   buf[3p+0] = (in.x, in.y)   buf[3p+1] = (in.z, tg.z)   buf[3p+2] = (tg.x, tg.y)
__device__ __forceinline__ void stage_group(const float* __restrict__ inputs,
                                            const float* __restrict__ target,
                                            int g, __half2* __restrict__ buf,
                                            int pt)   // producer thread id 0..255
{
    const float* in_slab = inputs + (size_t)g * CNT * 9;
    const float* tg_slab = target + (size_t)g * CNT * 9;
    #pragma unroll 8
    for (int k = 0; k < CNT / HALF_T; k++) {   // 32 iters
        const int p = pt + k * HALF_T;
        const float* ri = in_slab + (size_t)p * 9 + 3;
        const float* rt = tg_slab + (size_t)p * 9 + 3;
        float ix = __ldg(ri + 0), iy = __ldg(ri + 1), iz = __ldg(ri + 2);
        float tx = __ldg(rt + 0), ty = __ldg(rt + 1), tz = __ldg(rt + 2);
        buf[3 * p + 0] = __floats2half2_rn(ix, iy);
        buf[3 * p + 1] = __floats2half2_rn(iz, tz);
        buf[3 * p + 2] = __floats2half2_rn(tx, ty);
    }
}

__device__ __forceinline__ float consume_group(const int* __restrict__ left,
                                               const int* __restrict__ right,
                                               int g, const __half2* __restrict__ buf,
                                               int ct)  // consumer thread id 0..255
{
    const int* Lg = left  + (size_t)g * SPG;
    const int* Rg = right + (size_t)g * SPG;
    float acc = 0.0f;
    #pragma unroll 4
    for (int j = 0; j < SPG / HALF_T; j++) {   // 32 iters
        const int i = ct + j * HALF_T;
        const int l = __ldg(Lg + i) & (CNT - 1);
        const int r = __ldg(Rg + i) & (CNT - 1);

        float2 a  = __half22float2(buf[3 * l + 0]);   // in.xy (l)
        float2 mz = __half22float2(buf[3 * l + 1]);   // (in.z, tg.z) (l)
        float2 c  = __half22float2(buf[3 * l + 2]);   // tg.xy (l)
        float2 b  = __half22float2(buf[3 * r + 0]);
        float2 nz = __half22float2(buf[3 * r + 1]);
        float2 d  = __half22float2(buf[3 * r + 2]);

        float ux = a.x - b.x, uy = a.y - b.y, uz = mz.x - nz.x;
        float d_in = sqrtf(fmaf(ux, ux, fmaf(uy, uy, uz * uz)));

        float vx = c.x - d.x, vy = c.y - d.y, vz = mz.y - nz.y;
        float d_tg = sqrtf(fmaf(vx, vx, fmaf(vy, vy, vz * vz)));

        float t = d_in - d_tg;
        acc = fmaf(t, t, acc);
    }
    return acc;
}

__global__ void __launch_bounds__(TPB, 1)
rgn_pipelined_kernel(const float* __restrict__ inputs,
                     const float* __restrict__ target,
                     const int* __restrict__ left,
                     const int* __restrict__ right,
                     float* __restrict__ out,
                     int npairs, int ngroups)
{
    extern __shared__ unsigned char smem_raw[];
    __half2* buf0 = (__half2*)smem_raw;
    __half2* buf1 = buf0 + BUF_H2;

    const bool is_prod = (threadIdx.x >= HALF_T);
    const int  role_t  = is_prod ? (threadIdx.x - HALF_T) : threadIdx.x;

    // groups for this CTA: blockIdx.x + r*gridDim.x, r = 0..K-1
    const int K = (ngroups - blockIdx.x + gridDim.x - 1) / gridDim.x;

    float acc = 0.0f;
    for (int r = 0; r <= K; r++) {
        __syncthreads();
        if (is_prod) {
            if (r < K) {
                __half2* b = (r & 1) ? buf1 : buf0;
                stage_group(inputs, target, blockIdx.x + r * gridDim.x, b, role_t);
            }
        } else {
            if (r >= 1) {
                const __half2* b = ((r - 1) & 1) ? buf1 : buf0;
                acc += consume_group(left, right, blockIdx.x + (r - 1) * gridDim.x, b, role_t);
            }
        }
    }
    __syncthreads();

    // block reduce over all 512 threads (producers carry 0)
    #pragma unroll
    for (int off = 16; off > 0; off >>= 1)
        acc += __shfl_down_sync(0xFFFFFFFFu, acc, off);

    __shared__ float warp_sums[TPB / 32];
    const int lane = threadIdx.x & 31;
    const int wid  = threadIdx.x >> 5;
    if (lane == 0) warp_sums[wid] = acc;
    __syncthreads();

    if (wid == 0) {
        float s = (lane < TPB / 32) ? warp_sums[lane] : 0.0f;
        #pragma unroll
        for (int off = (TPB / 64); off > 0; off >>= 1)
            s += __shfl_down_sync(0xFFFFFFFFu, s, off);

        if (lane == 0) {
            atomicAdd(&g_acc, (double)s);
            __threadfence();
            unsigned int done = atomicAdd(&g_count, 1u);
            if (done == gridDim.x - 1) {
                out[0] = (float)(g_acc / (double)npairs);
                g_acc = 0.0;      // reset for next graph replay
                g_count = 0;
            }
        }
    }
}

extern "C" void kernel_launch(void* const* d_in, const int* in_sizes, int n_in,
                              void* d_out, int out_size) {
    const float* inputs = (const float*)d_in[0];
    const float* target = (const float*)d_in[1];
    const int*   left   = (const int*)d_in[2];
    const int*   right  = (const int*)d_in[3];
    float* out = (float*)d_out;

    int npairs  = in_sizes[2];
    int ngroups = npairs / SPG;   // 512

    static int num_sms = 0;
    if (num_sms == 0) {
        cudaDeviceProp prop;
        cudaGetDeviceProperties(&prop, 0);
        num_sms = prop.multiProcessorCount;   // 152 on GB300
    }
    int grid = num_sms;
    if (grid > ngroups) grid = ngroups;

    cudaFuncSetAttribute(rgn_pipelined_kernel,
                         cudaFuncAttributeMaxDynamicSharedMemorySize, SMEM_BYTES);

    rgn_pipelined_kernel<<<grid, TPB, SMEM_BYTES>>>(inputs, target, left, right,
                                                    out, npairs, ngroups);
}

// round 6
// speedup vs baseline: 1.8924x; 1.8924x over previous
#include <cuda_runtime.h>
#include <cuda_fp16.h>
#include <math.h>

#define TPB    1024
#define HALF_T 512               // producers = threads [512,1024), consumers = [0,512)
#define CNT    8192              // points per group
#define SPG    8192              // pairs per group
#define BUF_H2 (3 * CNT)         // half2 slots per buffer (12 B/point) = 96 KB
#define SMEM_BYTES (2 * BUF_H2 * 4)   // 192 KB double buffer

__device__ double g_acc = 0.0;
__device__ unsigned int g_count = 0;

// Interleaved layout per point p:
//   buf[3p+0] = (in.x, in.y)   buf[3p+1] = (in.z, tg.z)   buf[3p+2] = (tg.x, tg.y)
__device__ __forceinline__ void stage_group(const float* __restrict__ inputs,
                                            const float* __restrict__ target,
                                            int g, __half2* __restrict__ buf,
                                            int pt)   // producer thread id 0..511
{
    const float* in_slab = inputs + (size_t)g * CNT * 9;
    const float* tg_slab = target + (size_t)g * CNT * 9;
    #pragma unroll 4
    for (int k = 0; k < CNT / HALF_T; k++) {   // 16 iters
        const int p = pt + k * HALF_T;
        const float* ri = in_slab + (size_t)p * 9 + 3;
        const float* rt = tg_slab + (size_t)p * 9 + 3;
        float ix = __ldg(ri + 0), iy = __ldg(ri + 1), iz = __ldg(ri + 2);
        float tx = __ldg(rt + 0), ty = __ldg(rt + 1), tz = __ldg(rt + 2);
        buf[3 * p + 0] = __floats2half2_rn(ix, iy);
        buf[3 * p + 1] = __floats2half2_rn(iz, tz);
        buf[3 * p + 2] = __floats2half2_rn(tx, ty);
    }
}

__device__ __forceinline__ float pair_term(int l, int r, const __half2* __restrict__ buf)
{
    float2 a  = __half22float2(buf[3 * l + 0]);
    float2 mz = __half22float2(buf[3 * l + 1]);
    float2 c  = __half22float2(buf[3 * l + 2]);
    float2 b  = __half22float2(buf[3 * r + 0]);
    float2 nz = __half22float2(buf[3 * r + 1]);
    float2 d  = __half22float2(buf[3 * r + 2]);

    float ux = a.x - b.x, uy = a.y - b.y, uz = mz.x - nz.x;
    float d_in = sqrtf(fmaf(ux, ux, fmaf(uy, uy, uz * uz)));

    float vx = c.x - d.x, vy = c.y - d.y, vz = mz.y - nz.y;
    float d_tg = sqrtf(fmaf(vx, vx, fmaf(vy, vy, vz * vz)));

    float t = d_in - d_tg;
    return t * t;
}

__device__ __forceinline__ float consume_group(const int* __restrict__ left,
                                               const int* __restrict__ right,
                                               int g, const __half2* __restrict__ buf,
                                               int ct)  // consumer thread id 0..511
{
    const int4* Lg = (const int4*)(left  + (size_t)g * SPG);
    const int4* Rg = (const int4*)(right + (size_t)g * SPG);
    float acc = 0.0f;
    #pragma unroll
    for (int j = 0; j < SPG / (4 * HALF_T); j++) {   // 4 iters, 4 pairs each
        const int i = ct + j * HALF_T;
        int4 L = __ldg(Lg + i);
        int4 R = __ldg(Rg + i);
        acc += pair_term(L.x & (CNT - 1), R.x & (CNT - 1), buf);
        acc += pair_term(L.y & (CNT - 1), R.y & (CNT - 1), buf);
        acc += pair_term(L.z & (CNT - 1), R.z & (CNT - 1), buf);
        acc += pair_term(L.w & (CNT - 1), R.w & (CNT - 1), buf);
    }
    return acc;
}

__global__ void __launch_bounds__(TPB, 1)
rgn_ws_kernel(const float* __restrict__ inputs,
              const float* __restrict__ target,
              const int* __restrict__ left,
              const int* __restrict__ right,
              float* __restrict__ out,
              int npairs, int ngroups)
{
    extern __shared__ unsigned char smem_raw[];
    __half2* buf0 = (__half2*)smem_raw;
    __half2* buf1 = buf0 + BUF_H2;

    const bool is_prod = (threadIdx.x >= HALF_T);
    const int  role_t  = is_prod ? (threadIdx.x - HALF_T) : threadIdx.x;

    // groups for this CTA: blockIdx.x + r*gridDim.x, r = 0..K-1
    const int K = (ngroups - blockIdx.x + gridDim.x - 1) / gridDim.x;

    float acc = 0.0f;
    for (int r = 0; r <= K; r++) {
        __syncthreads();
        if (is_prod) {
            if (r < K) {
                __half2* b = (r & 1) ? buf1 : buf0;
                stage_group(inputs, target, blockIdx.x + r * gridDim.x, b, role_t);
            }
        } else {
            if (r >= 1) {
                const __half2* b = ((r - 1) & 1) ? buf1 : buf0;
                acc += consume_group(left, right, blockIdx.x + (r - 1) * gridDim.x, b, role_t);
            }
        }
    }
    __syncthreads();

    // block reduce (producers carry 0)
    #pragma unroll
    for (int off = 16; off > 0; off >>= 1)
        acc += __shfl_down_sync(0xFFFFFFFFu, acc, off);

    __shared__ float warp_sums[TPB / 32];
    const int lane = threadIdx.x & 31;
    const int wid  = threadIdx.x >> 5;
    if (lane == 0) warp_sums[wid] = acc;
    __syncthreads();

    if (wid == 0) {
        float s = (lane < TPB / 32) ? warp_sums[lane] : 0.0f;
        #pragma unroll
        for (int off = (TPB / 64); off > 0; off >>= 1)
            s += __shfl_down_sync(0xFFFFFFFFu, s, off);

        if (lane == 0) {
            atomicAdd(&g_acc, (double)s);
            __threadfence();
            unsigned int done = atomicAdd(&g_count, 1u);
            if (done == gridDim.x - 1) {
                out[0] = (float)(g_acc / (double)npairs);
                g_acc = 0.0;     // reset for next graph replay
                g_count = 0;
            }
        }
    }
}

extern "C" void kernel_launch(void* const* d_in, const int* in_sizes, int n_in,
                              void* d_out, int out_size) {
    const float* inputs = (const float*)d_in[0];
    const float* target = (const float*)d_in[1];
    const int*   left   = (const int*)d_in[2];
    const int*   right  = (const int*)d_in[3];
    float* out = (float*)d_out;

    int npairs  = in_sizes[2];
    int ngroups = npairs / SPG;   // 512

    static int num_sms = 0;
    if (num_sms == 0) {
        cudaDeviceProp prop;
        cudaGetDeviceProperties(&prop, 0);
        num_sms = prop.multiProcessorCount;   // 152 on GB300
    }
    int grid = num_sms;
    if (grid > ngroups) grid = ngroups;

    cudaFuncSetAttribute(rgn_ws_kernel,
                         cudaFuncAttributeMaxDynamicSharedMemorySize, SMEM_BYTES);

    rgn_ws_kernel<<<grid, TPB, SMEM_BYTES>>>(inputs, target, left, right,
                                             out, npairs, ngroups);
}